// round 12
// baseline (speedup 1.0000x reference)
#include <cuda_runtime.h>
#include <cuda_bf16.h>
#include <math.h>

// ---- Physical constants, folded at compile time ----
namespace mk {
constexpr double R_      = 3.0 * 0.0254;
constexpr double LSUM    = 0.129907 + 0.095724;
constexpr double G_      = 13.7;
constexpr double MASS_   = 12.0;
constexpr double MOI_    = MASS_ * (12.0 * 0.0254) * (12.0 * 0.0254) / 6.0;

constexpr double T_DUTY = 0.193 * G_;
constexpr double T_VEL  = G_ * 0.000304 * G_;
constexpr double T_FRIC = 0.00317 * G_;
constexpr double K_XYd  = 1.0 / (4.0 * R_ * MASS_);
constexpr double K_Wd   = 1.0 / (4.0 * LSUM * R_ * MOI_);

constexpr float INV_R = (float)(1.0 / R_);
constexpr float L_R   = (float)(LSUM / R_);
constexpr float EPS   = 0.01f;

// Collapsed-chain constants (pinv sign patterns telescope duty/damping paths)
constexpr float A_XY = (float)(4.0 * K_XYd * T_DUTY);
constexpr float B_XY = (float)(4.0 * K_XYd * T_VEL / R_);
constexpr float C_XY = (float)(K_XYd * T_FRIC);
constexpr float A_W  = (float)(4.0 * K_Wd * T_DUTY);
constexpr float B_W  = (float)(4.0 * K_Wd * T_VEL * LSUM / R_);
constexpr float C_W  = (float)(K_Wd * T_FRIC);
}

// MUFU-path math: |theta| <~ 5.5 for N(0,1) inputs; measured rel_err 8e-8
// against the 1e-3 tolerance with this path.
__device__ __forceinline__ void fast_sincos(float x, float& s, float& c) {
    asm("sin.approx.f32 %0, %1;" : "=f"(s) : "f"(x));
    asm("cos.approx.f32 %0, %1;" : "=f"(c) : "f"(x));
}
__device__ __forceinline__ float fast_rsqrt(float x) {
    float r;
    asm("rsqrt.approx.f32 %0, %1;" : "=f"(r) : "f"(x));
    return r;
}

__device__ __forceinline__ void l2_prefetch(const void* p) {
    asm volatile("prefetch.global.L2 [%0];" :: "l"(p));
}

__device__ __forceinline__ void mecanum_row(
    float theta, float vx, float vy, float wz,
    float u0, float u1, float u2,
    float& ax, float& ay, float& aw)
{
    float st, ct;
    fast_sincos(theta, st, ct);

    // local velocity (rotation by -theta)
    float lvx =  ct * vx + st * vy;
    float lvy = -st * vx + ct * vy;

    // wheel velocities (needed only for the softsign friction terms)
    float p  = mk::INV_R * (lvx + lvy);
    float m  = mk::INV_R * (lvx - lvy);
    float lz = mk::L_R * wz;
    float w0 = m - lz;
    float w1 = p + lz;
    float w2 = p - lz;
    float w3 = m + lz;

    float ss0 = w0 * fast_rsqrt(w0 * w0 + mk::EPS);
    float ss1 = w1 * fast_rsqrt(w1 * w1 + mk::EPS);
    float ss2 = w2 * fast_rsqrt(w2 * w2 + mk::EPS);
    float ss3 = w3 * fast_rsqrt(w3 * w3 + mk::EPS);

    // sign-pattern sums:  S0 = ++++ , S1 = -++- , S2 = -+-+
    float a = ss0 + ss3, b = ss1 + ss2;
    float S0 = a + b;
    float S1 = b - a;
    float S2 = (ss1 - ss2) + (ss3 - ss0);

    // collapsed local acceleration
    float la0 = mk::A_XY * u0 - mk::B_XY * lvx - mk::C_XY * S0;
    float la1 = mk::A_XY * u1 - mk::B_XY * lvy - mk::C_XY * S1;
    float la2 = mk::A_W  * u2 - mk::B_W  * wz  - mk::C_W  * S2;

    // rotate back by +theta (A^T)
    ax = ct * la0 - st * la1;
    ay = st * la0 + ct * la1;
    aw = la2;
}

// ---- R11 body + one-wave-ahead L2 prefetch ----
// Per row: 2x float2 state loads (8-aligned; unused x,y never read), 3 scalar
// ctrl loads, 3x float2 __stcs streaming stores (write-only output stays
// evict-first so inputs remain L2-resident across graph replays).
// NEW: each block prefetches the INPUT lines of the block one full wave ahead
// (D = 148 SMs x 8 CTAs). 256 rows/block = 48 state lines + 24 ctrl lines, so
// 72 of 256 threads issue exactly one register-free prefetch.
constexpr int TPB     = 256;
constexpr int WAVE    = 148 * 8;     // concurrent CTAs at 8/SM occupancy
constexpr int SLINES  = TPB * 24 / 128;   // 48 state lines per block
constexpr int CLINES  = TPB * 12 / 128;   // 24 ctrl lines per block

__global__ void __launch_bounds__(TPB, 8)
mecanum_row_kernel(const float* __restrict__ state,
                   const float* __restrict__ ctrl,
                   float* __restrict__ out,
                   int B)
{
    int i = blockIdx.x * TPB + threadIdx.x;

    // --- prefetch inputs for block (blockIdx.x + WAVE) ---
    {
        int t = threadIdx.x;
        long long r0 = ((long long)blockIdx.x + WAVE) * TPB;  // first row of ahead block
        if (t < SLINES) {
            long long byte = r0 * 24 + (long long)t * 128;
            if (byte < (long long)B * 24)
                l2_prefetch((const char*)state + byte);
        } else if (t < SLINES + CLINES) {
            long long byte = r0 * 12 + (long long)(t - SLINES) * 128;
            if (byte < (long long)B * 12)
                l2_prefetch((const char*)ctrl + byte);
        }
    }

    if (i >= B) return;

    const float2* s2 = reinterpret_cast<const float2*>(state + 6 * (size_t)i + 2);
    float2 tv = __ldg(s2 + 0);        // theta, vx
    float2 vw = __ldg(s2 + 1);        // vy, wz

    const float* u = ctrl + 3 * (size_t)i;
    float u0 = __ldg(u + 0), u1 = __ldg(u + 1), u2 = __ldg(u + 2);

    float ax, ay, aw;
    mecanum_row(tv.x, tv.y, vw.x, vw.y, u0, u1, u2, ax, ay, aw);

    float2* o2 = reinterpret_cast<float2*>(out + 6 * (size_t)i);
    __stcs(o2 + 0, make_float2(tv.y, vw.x));   // vx, vy
    __stcs(o2 + 1, make_float2(vw.y, ax));     // wz, ax
    __stcs(o2 + 2, make_float2(ay, aw));       // ay, aw
}

extern "C" void kernel_launch(void* const* d_in, const int* in_sizes, int n_in,
                              void* d_out, int out_size)
{
    // metadata order: t (1), state (B*6), control_duty (B*3)
    const float* state = (const float*)d_in[1];
    const float* ctrl  = (const float*)d_in[2];
    float* out = (float*)d_out;
    int B = in_sizes[1] / 6;

    int blocks = (B + TPB - 1) / TPB;
    mecanum_row_kernel<<<blocks, TPB>>>(state, ctrl, out, B);
}

// round 13
// speedup vs baseline: 1.1366x; 1.1366x over previous
#include <cuda_runtime.h>
#include <cuda_bf16.h>
#include <math.h>

// ---- Physical constants, folded at compile time ----
namespace mk {
constexpr double R_      = 3.0 * 0.0254;
constexpr double LSUM    = 0.129907 + 0.095724;
constexpr double G_      = 13.7;
constexpr double MASS_   = 12.0;
constexpr double MOI_    = MASS_ * (12.0 * 0.0254) * (12.0 * 0.0254) / 6.0;

constexpr double T_DUTY = 0.193 * G_;
constexpr double T_VEL  = G_ * 0.000304 * G_;
constexpr double T_FRIC = 0.00317 * G_;
constexpr double K_XYd  = 1.0 / (4.0 * R_ * MASS_);
constexpr double K_Wd   = 1.0 / (4.0 * LSUM * R_ * MOI_);

constexpr float INV_R = (float)(1.0 / R_);
constexpr float L_R   = (float)(LSUM / R_);
constexpr float EPS   = 0.01f;

// Collapsed-chain constants (analytic pinv sign patterns make the duty and
// damping paths telescope to single FMAs; only softsign needs per-wheel work)
constexpr float A_XY = (float)(4.0 * K_XYd * T_DUTY);
constexpr float B_XY = (float)(4.0 * K_XYd * T_VEL / R_);
constexpr float C_XY = (float)(K_XYd * T_FRIC);
constexpr float A_W  = (float)(4.0 * K_Wd * T_DUTY);
constexpr float B_W  = (float)(4.0 * K_Wd * T_VEL * LSUM / R_);
constexpr float C_W  = (float)(K_Wd * T_FRIC);
}

// MUFU-path math: inputs are N(0,1) (|theta| <~ 5.5) where sin/cos.approx are
// ~1e-6 accurate; measured rel_err 8e-8 against the 1e-3 tolerance.
__device__ __forceinline__ void fast_sincos(float x, float& s, float& c) {
    asm("sin.approx.f32 %0, %1;" : "=f"(s) : "f"(x));
    asm("cos.approx.f32 %0, %1;" : "=f"(c) : "f"(x));
}
__device__ __forceinline__ float fast_rsqrt(float x) {
    float r;
    asm("rsqrt.approx.f32 %0, %1;" : "=f"(r) : "f"(x));
    return r;
}

__device__ __forceinline__ void mecanum_row(
    float theta, float vx, float vy, float wz,
    float u0, float u1, float u2,
    float& ax, float& ay, float& aw)
{
    float st, ct;
    fast_sincos(theta, st, ct);

    // local velocity (rotation by -theta)
    float lvx =  ct * vx + st * vy;
    float lvy = -st * vx + ct * vy;

    // wheel velocities (needed only for the softsign friction terms)
    float p  = mk::INV_R * (lvx + lvy);
    float m  = mk::INV_R * (lvx - lvy);
    float lz = mk::L_R * wz;
    float w0 = m - lz;
    float w1 = p + lz;
    float w2 = p - lz;
    float w3 = m + lz;

    float ss0 = w0 * fast_rsqrt(w0 * w0 + mk::EPS);
    float ss1 = w1 * fast_rsqrt(w1 * w1 + mk::EPS);
    float ss2 = w2 * fast_rsqrt(w2 * w2 + mk::EPS);
    float ss3 = w3 * fast_rsqrt(w3 * w3 + mk::EPS);

    // sign-pattern sums:  S0 = ++++ , S1 = -++- , S2 = -+-+
    float a = ss0 + ss3, b = ss1 + ss2;
    float S0 = a + b;
    float S1 = b - a;
    float S2 = (ss1 - ss2) + (ss3 - ss0);

    // collapsed local acceleration
    float la0 = mk::A_XY * u0 - mk::B_XY * lvx - mk::C_XY * S0;
    float la1 = mk::A_XY * u1 - mk::B_XY * lvy - mk::C_XY * S1;
    float la2 = mk::A_W  * u2 - mk::B_W  * wz  - mk::C_W  * S2;

    // rotate back by +theta (A^T)
    ax = ct * la0 - st * la1;
    ay = st * la0 + ct * la1;
    aw = la2;
}

// ---- Final form (R11): one row per thread, minimal body ----
// Per row: 2x float2 state loads via the nc path (8-aligned; the unused x,y
// fields are never loaded), 3 scalar ctrl loads (nc), 3x float2 __stcs
// streaming stores (write-only output -> evict-first keeps the 72MB of
// inputs L2-resident across graph replays). 29 regs, 8 CTAs/SM.
// Measured floor for this AoS layout: every structural alternative
// (smem staging, row pairing, dual-region ILP, grid-stride persistence,
// L2 prefetch) regressed; arithmetic reduction and occupancy increases
// were neutral.
__global__ void __launch_bounds__(256, 8)
mecanum_row_kernel(const float* __restrict__ state,
                   const float* __restrict__ ctrl,
                   float* __restrict__ out,
                   int B)
{
    int i = blockIdx.x * blockDim.x + threadIdx.x;
    if (i >= B) return;

    const float2* s2 = reinterpret_cast<const float2*>(state + 6 * (size_t)i + 2);
    float2 tv = __ldg(s2 + 0);        // theta, vx
    float2 vw = __ldg(s2 + 1);        // vy, wz

    const float* u = ctrl + 3 * (size_t)i;
    float u0 = __ldg(u + 0), u1 = __ldg(u + 1), u2 = __ldg(u + 2);

    float ax, ay, aw;
    mecanum_row(tv.x, tv.y, vw.x, vw.y, u0, u1, u2, ax, ay, aw);

    float2* o2 = reinterpret_cast<float2*>(out + 6 * (size_t)i);
    __stcs(o2 + 0, make_float2(tv.y, vw.x));   // vx, vy
    __stcs(o2 + 1, make_float2(vw.y, ax));     // wz, ax
    __stcs(o2 + 2, make_float2(ay, aw));       // ay, aw
}

extern "C" void kernel_launch(void* const* d_in, const int* in_sizes, int n_in,
                              void* d_out, int out_size)
{
    // metadata order: t (1), state (B*6), control_duty (B*3)
    const float* state = (const float*)d_in[1];
    const float* ctrl  = (const float*)d_in[2];
    float* out = (float*)d_out;
    int B = in_sizes[1] / 6;

    int threads = 256;
    int blocks = (B + threads - 1) / threads;
    mecanum_row_kernel<<<blocks, threads>>>(state, ctrl, out, B);
}